// round 12
// baseline (speedup 1.0000x reference)
#include <cuda_runtime.h>
#include <cuda_bf16.h>
#include <mma.h>
#include <cstdint>

using namespace nvcuda;

#define T_LEN 2048
#define B_SZ  2
#define EMB   512
#define ROWS  4096       // B*T
#define HEADS 8
#define HDIM  64
#define NHASH 2
#define FULLMASK 0xffffffffu

// ---------------------------------------------------------------------------
// Scratch
// ---------------------------------------------------------------------------
__device__ float g_Q[ROWS * EMB];
__device__ float g_K[ROWS * EMB];
__device__ float g_V[ROWS * EMB];
__device__ unsigned char g_qh[NHASH * B_SZ * HEADS * T_LEN];
__device__ unsigned char g_kh[NHASH * B_SZ * HEADS * T_LEN];
__device__ float g_att[NHASH][ROWS * EMB];
__device__ int g_qstart[32][65];
__device__ int g_kstart[32][65];
__device__ unsigned short g_qlist[32 * T_LEN];
__device__ unsigned short g_klist[32 * T_LEN];
// pre-split bf16 operands for the tensor-core GEMMs
__device__ __nv_bfloat16 g_Ah[ROWS * EMB];
__device__ __nv_bfloat16 g_Al[ROWS * EMB];
__device__ __nv_bfloat16 g_Wh[EMB * EMB];
__device__ __nv_bfloat16 g_Wl[EMB * EMB];

// ---------------------------------------------------------------------------
// helpers
// ---------------------------------------------------------------------------
__device__ __forceinline__ float2 ffma2(float2 a, float2 b, float2 c)
{
    unsigned long long ua = *reinterpret_cast<unsigned long long*>(&a);
    unsigned long long ub = *reinterpret_cast<unsigned long long*>(&b);
    unsigned long long uc = *reinterpret_cast<unsigned long long*>(&c);
    unsigned long long ud;
    asm("fma.rn.f32x2 %0, %1, %2, %3;" : "=l"(ud) : "l"(ua), "l"(ub), "l"(uc));
    return *reinterpret_cast<float2*>(&ud);
}

__device__ __forceinline__ void cp_async16(void* smem_dst, const void* gsrc)
{
    uint32_t s = (uint32_t)__cvta_generic_to_shared(smem_dst);
    asm volatile("cp.async.cg.shared.global [%0], [%1], 16;" :: "r"(s), "l"(gsrc));
}
#define CP_COMMIT() asm volatile("cp.async.commit_group;" ::: "memory")
#define CP_WAIT(n)  asm volatile("cp.async.wait_group %0;" :: "n"(n) : "memory")

#define AS2_STRIDE 258
#define BSX_STRIDE 132
#define QKV_SMEM ((2 * 16 * AS2_STRIDE + 2 * 16 * BSX_STRIDE) * 4)

__device__ __forceinline__ void tile_fma2(const float* __restrict__ A2,
                                          const float* __restrict__ Bx,
                                          float2 acc[8][4], int tx, int ty)
{
#pragma unroll
    for (int k = 0; k < 16; k++) {
        const float* ar = A2 + k * AS2_STRIDE;
        const float* br = Bx + k * BSX_STRIDE;
        float2 avd[8], bv2[4];
#pragma unroll
        for (int i = 0; i < 8; i++)
            avd[i] = *reinterpret_cast<const float2*>(ar + 2 * (ty * 8 + i));
#pragma unroll
        for (int p = 0; p < 4; p++)
            bv2[p] = *reinterpret_cast<const float2*>(br + p * 32 + tx * 2);
#pragma unroll
        for (int i = 0; i < 8; i++)
#pragma unroll
            for (int p = 0; p < 4; p++)
                acc[i][p] = ffma2(avd[i], bv2[p], acc[i][p]);
    }
}

// ---------------------------------------------------------------------------
// Kernel 1: Q/K projections (EXACT fp32 — LSH argmax is flip-sensitive).
// ---------------------------------------------------------------------------
__global__ __launch_bounds__(256, 2) void gemm_qk(
    const float* __restrict__ Xq, const float* __restrict__ Xk,
    const float* __restrict__ Wq, const float* __restrict__ Wk,
    const float* __restrict__ bq, const float* __restrict__ bk)
{
    extern __shared__ float sm[];
    float* A2 = sm;
    float* Bx = sm + 2 * 16 * AS2_STRIDE;

    const int tid = threadIdx.x;
    const int bn = blockIdx.x;
    const int bm = blockIdx.y;
    const int z  = blockIdx.z;
    const int tx = tid & 15, ty = tid >> 4;

    const float* X = (z == 0) ? Xq : Xk;
    const float* W = (z == 0) ? Wq : Wk;
    const float* bias = (z == 0) ? bq : bk;
    float* outp = (z == 0) ? g_Q : g_K;

    const int rr = tid >> 1;
    const int kb = (tid & 1) * 8;
    const int r = bm * 128 + rr;
    const int src = (r & 1) * T_LEN + (r >> 1);
    const float* Aptr = X + (size_t)src * EMB + kb;
    const float* Bptr = W + (size_t)(bn * 128 + rr) * EMB + kb;

    float2 acc[8][4];
#pragma unroll
    for (int i = 0; i < 8; i++)
#pragma unroll
        for (int p = 0; p < 4; p++) acc[i][p] = make_float2(0.f, 0.f);

    float4 ra0 = *reinterpret_cast<const float4*>(Aptr);
    float4 ra1 = *reinterpret_cast<const float4*>(Aptr + 4);
    float4 rb0 = *reinterpret_cast<const float4*>(Bptr);
    float4 rb1 = *reinterpret_cast<const float4*>(Bptr + 4);

    {
        float va[8] = {ra0.x, ra0.y, ra0.z, ra0.w, ra1.x, ra1.y, ra1.z, ra1.w};
        float vb[8] = {rb0.x, rb0.y, rb0.z, rb0.w, rb1.x, rb1.y, rb1.z, rb1.w};
#pragma unroll
        for (int c = 0; c < 8; c++) {
            float* pa = A2 + (kb + c) * AS2_STRIDE + 2 * rr;
            pa[0] = va[c]; pa[1] = va[c];
            Bx[(kb + c) * BSX_STRIDE + rr] = vb[c];
        }
    }
    __syncthreads();

    const int NS = EMB / 16;
    for (int s = 0; s < NS; s++) {
        const int cur = s & 1;
        if (s + 1 < NS) {
            ra0 = *reinterpret_cast<const float4*>(Aptr + (s + 1) * 16);
            ra1 = *reinterpret_cast<const float4*>(Aptr + (s + 1) * 16 + 4);
            rb0 = *reinterpret_cast<const float4*>(Bptr + (s + 1) * 16);
            rb1 = *reinterpret_cast<const float4*>(Bptr + (s + 1) * 16 + 4);
        }
        tile_fma2(A2 + cur * 16 * AS2_STRIDE, Bx + cur * 16 * BSX_STRIDE, acc, tx, ty);
        if (s + 1 < NS) {
            __syncthreads();
            const int nxt = cur ^ 1;
            float va[8] = {ra0.x, ra0.y, ra0.z, ra0.w, ra1.x, ra1.y, ra1.z, ra1.w};
            float vb[8] = {rb0.x, rb0.y, rb0.z, rb0.w, rb1.x, rb1.y, rb1.z, rb1.w};
#pragma unroll
            for (int c = 0; c < 8; c++) {
                float* pa = A2 + (nxt * 16 + kb + c) * AS2_STRIDE + 2 * rr;
                pa[0] = va[c]; pa[1] = va[c];
                Bx[(nxt * 16 + kb + c) * BSX_STRIDE + rr] = vb[c];
            }
            __syncthreads();
        }
    }

    float2 bb2[4];
#pragma unroll
    for (int p = 0; p < 4; p++)
        bb2[p] = *reinterpret_cast<const float2*>(bias + bn * 128 + p * 32 + tx * 2);
#pragma unroll
    for (int i = 0; i < 8; i++) {
        int ro = bm * 128 + ty * 8 + i;
        float* op = outp + (size_t)ro * EMB + bn * 128;
#pragma unroll
        for (int p = 0; p < 4; p++) {
            float2 v = acc[i][p];
            v.x += bb2[p].x; v.y += bb2[p].y;
            *reinterpret_cast<float2*>(op + p * 32 + tx * 2) = v;
        }
    }
}

// ---------------------------------------------------------------------------
// Split kernels: fp32 -> (hi, lo) bf16 pairs, vectorized.
// ---------------------------------------------------------------------------
__device__ __forceinline__ void split_store4(__nv_bfloat16* dh, __nv_bfloat16* dl,
                                             float4 v)
{
    float h0 = __bfloat162float(__float2bfloat16(v.x));
    float h1 = __bfloat162float(__float2bfloat16(v.y));
    float h2 = __bfloat162float(__float2bfloat16(v.z));
    float h3 = __bfloat162float(__float2bfloat16(v.w));
    __nv_bfloat162 a, b;
    a.x = __float2bfloat16(v.x); a.y = __float2bfloat16(v.y);
    b.x = __float2bfloat16(v.z); b.y = __float2bfloat16(v.w);
    *reinterpret_cast<__nv_bfloat162*>(dh)     = a;
    *reinterpret_cast<__nv_bfloat162*>(dh + 2) = b;
    __nv_bfloat162 c, d;
    c.x = __float2bfloat16(v.x - h0); c.y = __float2bfloat16(v.y - h1);
    d.x = __float2bfloat16(v.z - h2); d.y = __float2bfloat16(v.w - h3);
    *reinterpret_cast<__nv_bfloat162*>(dl)     = c;
    *reinterpret_cast<__nv_bfloat162*>(dl + 2) = d;
}

__global__ __launch_bounds__(256) void split_v_kernel(const float* __restrict__ value)
{
    int idx = blockIdx.x * 256 + threadIdx.x;
    int f = idx >> 7;
    int c = (idx & 127) * 4;
    int srcr = (f & 1) * T_LEN + (f >> 1);
    float4 v = *reinterpret_cast<const float4*>(value + (size_t)srcr * EMB + c);
    split_store4(g_Ah + (size_t)f * EMB + c, g_Al + (size_t)f * EMB + c, v);
}

__global__ __launch_bounds__(256) void split_w_kernel(const float* __restrict__ W)
{
    int idx = blockIdx.x * 256 + threadIdx.x;
    int rr = idx >> 7;
    int c = (idx & 127) * 4;
    float4 v = *reinterpret_cast<const float4*>(W + (size_t)rr * EMB + c);
    split_store4(g_Wh + (size_t)rr * EMB + c, g_Wl + (size_t)rr * EMB + c, v);
}

__global__ __launch_bounds__(256) void split_att_kernel()
{
    int idx = blockIdx.x * 256 + threadIdx.x;
    int f = idx >> 7;
    int c = (idx & 127) * 4;
    size_t o = (size_t)f * EMB + c;
    float4 x = *reinterpret_cast<const float4*>(&g_att[0][o]);
    float4 y = *reinterpret_cast<const float4*>(&g_att[1][o]);
    x.x = 0.5f * (x.x + y.x); x.y = 0.5f * (x.y + y.y);
    x.z = 0.5f * (x.z + y.z); x.w = 0.5f * (x.w + y.w);
    split_store4(g_Ah + o, g_Al + o, x);
}

// ---------------------------------------------------------------------------
// Kernel TC: bf16 split tensor-core GEMM, cp.async double-buffered.
// C = A @ W^T + bias; 3 MMAs (hh + hl + lh).
// MODE 0: dst = g_V. MODE 1: dst = out w/ (nb,nt)->(nt,nb).
// Block 128x128, BK=64, 8 warps (4m x 2n), warp = 32x64 via 2x4 frags.
// ---------------------------------------------------------------------------
#define TCS2 72                          // bf16 smem stride (144 B)
#define OBS  72                          // fp32 epilogue stride (288 B)
#define STG_ELE (128 * TCS2)             // elements per array per stage
#define STG_TOT (4 * STG_ELE)            // elements per stage (4 arrays)
#define TC_SMEM3 (2 * STG_TOT * 2)       // 147456 B (2 stages)

template<int MODE>
__global__ __launch_bounds__(256) void gemm_tc(float* __restrict__ out,
                                               const float* __restrict__ bias)
{
    extern __shared__ char raw[];
    __nv_bfloat16* base = reinterpret_cast<__nv_bfloat16*>(raw);
    float* obuf = reinterpret_cast<float*>(raw);

    const int tid = threadIdx.x;
    const int bn = blockIdx.x;
    const int bm = blockIdx.y;
    const int w  = tid >> 5;
    const int wm = w & 3;
    const int wn = w >> 2;

    wmma::fragment<wmma::accumulator, 16, 16, 16, float> acc[2][4];
#pragma unroll
    for (int im = 0; im < 2; im++)
#pragma unroll
        for (int jn = 0; jn < 4; jn++) wmma::fill_fragment(acc[im][jn], 0.f);

    // per-thread staging coords: 4 slots, each covering (row, 8-bf16 segment)
    // stage buffer layout: [buf][arr][128][TCS2], arr: 0=Ah 1=Al 2=Bh 3=Bl
    const int NSTG = EMB / 64;   // 8

    auto issue_stage = [&](int buf, int ks) {
        __nv_bfloat16* dst = base + buf * STG_TOT;
#pragma unroll
        for (int i = 0; i < 4; i++) {
            int idx = tid + i * 256;          // 0..1023
            int row = idx >> 3;               // 0..127
            int seg = idx & 7;                // 8-bf16 slot
            size_t ga = (size_t)(bm * 128 + row) * EMB + ks + seg * 8;
            size_t gb = (size_t)(bn * 128 + row) * EMB + ks + seg * 8;
            int so = row * TCS2 + seg * 8;
            cp_async16(dst + 0 * STG_ELE + so, g_Ah + ga);
            cp_async16(dst + 1 * STG_ELE + so, g_Al + ga);
            cp_async16(dst + 2 * STG_ELE + so, g_Wh + gb);
            cp_async16(dst + 3 * STG_ELE + so, g_Wl + gb);
        }
        CP_COMMIT();
    };

    issue_stage(0, 0);

    for (int s = 0; s < NSTG; s++) {
        if (s + 1 < NSTG) {
            issue_stage((s + 1) & 1, (s + 1) * 64);
            CP_WAIT(1);
        } else {
            CP_WAIT(0);
        }
        __syncthreads();

        const __nv_bfloat16* Ah = base + (s & 1) * STG_TOT + 0 * STG_ELE;
        const __nv_bfloat16* Al = base + (s & 1) * STG_TOT + 1 * STG_ELE;
        const __nv_bfloat16* Bh = base + (s & 1) * STG_TOT + 2 * STG_ELE;
        const __nv_bfloat16* Bl = base + (s & 1) * STG_TOT + 3 * STG_ELE;

#pragma unroll
        for (int kk = 0; kk < 4; kk++) {
            wmma::fragment<wmma::matrix_a, 16, 16, 16, __nv_bfloat16, wmma::row_major> ah[2], al[2];
#pragma unroll
            for (int im = 0; im < 2; im++) {
                wmma::load_matrix_sync(ah[im], Ah + (wm * 32 + im * 16) * TCS2 + kk * 16, TCS2);
                wmma::load_matrix_sync(al[im], Al + (wm * 32 + im * 16) * TCS2 + kk * 16, TCS2);
            }
#pragma unroll
            for (int jn = 0; jn < 4; jn++) {
                wmma::fragment<wmma::matrix_b, 16, 16, 16, __nv_bfloat16, wmma::col_major> bh, bl;
                wmma::load_matrix_sync(bh, Bh + (wn * 64 + jn * 16) * TCS2 + kk * 16, TCS2);
                wmma::load_matrix_sync(bl, Bl + (wn * 64 + jn * 16) * TCS2 + kk * 16, TCS2);
#pragma unroll
                for (int im = 0; im < 2; im++) {
                    wmma::mma_sync(acc[im][jn], ah[im], bh, acc[im][jn]);
                    wmma::mma_sync(acc[im][jn], ah[im], bl, acc[im][jn]);
                    wmma::mma_sync(acc[im][jn], al[im], bh, acc[im][jn]);
                }
            }
        }
        __syncthreads();   // protect buffer (s&1) before stage s+2 reuses it
    }

    float* dstp = (MODE == 0) ? g_V : out;

    // epilogue: two 128x64 halves through smem, exact fp32 bias add
#pragma unroll
    for (int half = 0; half < 2; half++) {
        __syncthreads();
        if (wn == half) {
#pragma unroll
            for (int im = 0; im < 2; im++)
#pragma unroll
                for (int jn = 0; jn < 4; jn++)
                    wmma::store_matrix_sync(obuf + (wm * 32 + im * 16) * OBS + jn * 16,
                                            acc[im][jn], OBS, wmma::mem_row_major);
        }
        __syncthreads();
#pragma unroll
        for (int it = 0; it < 8; it++) {
            int idx = tid + it * 256;
            int row = idx >> 4;
            int c4  = idx & 15;
            float4 v = *reinterpret_cast<const float4*>(&obuf[row * OBS + c4 * 4]);
            int colg = bn * 128 + half * 64 + c4 * 4;
            v.x += bias[colg + 0]; v.y += bias[colg + 1];
            v.z += bias[colg + 2]; v.w += bias[colg + 3];
            int ro = bm * 128 + row;
            int g = (MODE == 1) ? ((ro & 2047) * B_SZ + (ro >> 11)) : ro;
            *reinterpret_cast<float4*>(dstp + (size_t)g * EMB + colg) = v;
        }
    }
}

// ---------------------------------------------------------------------------
// Kernel 2: LSH hashing GEMM (64x128 tile) + fused argmax (exact fp32).
// ---------------------------------------------------------------------------
__global__ __launch_bounds__(256) void hash_gemm(const float* __restrict__ lshW,
                                                 const float* __restrict__ lshb)
{
    __shared__ float As2h[16][130];
    __shared__ float Bsh[16][132];
    const int tid = threadIdx.x;
    const int bm = blockIdx.x;
    const int tensor = blockIdx.y;
    const int tx = tid & 15, ty = tid >> 4;

    const float* A = tensor ? g_K : g_Q;
    unsigned char* dst = tensor ? g_kh : g_qh;

    float2 acc[4][4];
#pragma unroll
    for (int i = 0; i < 4; i++)
#pragma unroll
        for (int p = 0; p < 4; p++) acc[i][p] = make_float2(0.f, 0.f);

    for (int kk = 0; kk < 64; kk += 16) {
        {
            int arr = tid >> 2, ak4 = tid & 3;
            float4 a = *reinterpret_cast<const float4*>(A + (size_t)(bm * 64 + arr) * 64 + kk + ak4 * 4);
            float va[4] = {a.x, a.y, a.z, a.w};
#pragma unroll
            for (int c = 0; c < 4; c++) {
                As2h[ak4 * 4 + c][2 * arr] = va[c];
                As2h[ak4 * 4 + c][2 * arr + 1] = va[c];
            }
        }
#pragma unroll
        for (int i = 0; i < 2; i++) {
            int idx = tid * 2 + i;
            int rr = idx >> 2, bk4 = idx & 3;
            float4 b = *reinterpret_cast<const float4*>(lshW + (size_t)rr * 64 + kk + bk4 * 4);
            Bsh[bk4 * 4 + 0][rr] = b.x; Bsh[bk4 * 4 + 1][rr] = b.y;
            Bsh[bk4 * 4 + 2][rr] = b.z; Bsh[bk4 * 4 + 3][rr] = b.w;
        }
        __syncthreads();
#pragma unroll
        for (int k = 0; k < 16; k++) {
            float2 avd[4], bv2[4];
#pragma unroll
            for (int i = 0; i < 4; i++)
                avd[i] = *reinterpret_cast<const float2*>(&As2h[k][2 * (ty * 4 + i)]);
#pragma unroll
            for (int p = 0; p < 4; p++)
                bv2[p] = *reinterpret_cast<const float2*>(&Bsh[k][p * 32 + tx * 2]);
#pragma unroll
            for (int i = 0; i < 4; i++)
#pragma unroll
                for (int p = 0; p < 4; p++)
                    acc[i][p] = ffma2(avd[i], bv2[p], acc[i][p]);
        }
        __syncthreads();
    }

    float2 bb2[4];
#pragma unroll
    for (int p = 0; p < 4; p++)
        bb2[p] = *reinterpret_cast<const float2*>(lshb + p * 32 + tx * 2);

#pragma unroll
    for (int i = 0; i < 4; i++) {
        const int m  = bm * 64 + ty * 4 + i;
        const int r  = m >> 3, h = m & 7;
        const int nb = r >> 11, nt = r & 2047;
#pragma unroll
        for (int hh = 0; hh < 2; hh++) {
            float2 c0 = acc[i][2 * hh];
            float2 c1 = acc[i][2 * hh + 1];
            c0.x += bb2[2 * hh].x;     c0.y += bb2[2 * hh].y;
            c1.x += bb2[2 * hh + 1].x; c1.y += bb2[2 * hh + 1].y;
            float bvv = c0.x; int bi = tx * 2;
            if (c0.y > bvv) { bvv = c0.y; bi = tx * 2 + 1; }
            if (c1.x > bvv) { bvv = c1.x; bi = 32 + tx * 2; }
            if (c1.y > bvv) { bvv = c1.y; bi = 33 + tx * 2; }
#pragma unroll
            for (int off = 1; off < 16; off <<= 1) {
                float ov = __shfl_xor_sync(FULLMASK, bvv, off);
                int   oi = __shfl_xor_sync(FULLMASK, bi, off);
                if (ov > bvv || (ov == bvv && oi < bi)) { bvv = ov; bi = oi; }
            }
            if (tx == 0)
                dst[((hh * B_SZ + nb) * HEADS + h) * T_LEN + nt] = (unsigned char)bi;
        }
    }
}

// ---------------------------------------------------------------------------
// Kernel 3: bucketize
// ---------------------------------------------------------------------------
__global__ __launch_bounds__(256) void bucketize_kernel()
{
    __shared__ int cnt[2][64];
    __shared__ int off[2][64];
    const int combo = blockIdx.x;
    const int tid = threadIdx.x;

    for (int i = tid; i < 128; i += 256) cnt[i >> 6][i & 63] = 0;
    __syncthreads();

    const unsigned char* qh = g_qh + combo * T_LEN;
    const unsigned char* kh = g_kh + combo * T_LEN;
    for (int i = tid; i < T_LEN; i += 256) {
        atomicAdd(&cnt[0][qh[i]], 1);
        atomicAdd(&cnt[1][kh[i]], 1);
    }
    __syncthreads();

    if (tid == 0) {
        int s = 0;
        for (int j = 0; j < 64; j++) { g_qstart[combo][j] = s; off[0][j] = s; s += cnt[0][j]; }
        g_qstart[combo][64] = s;
    }
    if (tid == 32) {
        int s = 0;
        for (int j = 0; j < 64; j++) { g_kstart[combo][j] = s; off[1][j] = s; s += cnt[1][j]; }
        g_kstart[combo][64] = s;
    }
    __syncthreads();

    for (int i = tid; i < T_LEN; i += 256) {
        int p = atomicAdd(&off[0][qh[i]], 1);
        g_qlist[combo * T_LEN + p] = (unsigned short)i;
        p = atomicAdd(&off[1][kh[i]], 1);
        g_klist[combo * T_LEN + p] = (unsigned short)i;
    }
}

// ---------------------------------------------------------------------------
// Kernel 4: per-bucket flash attention, 32x32 tiles.
// ---------------------------------------------------------------------------
#define QS  68
#define KSK 34
#define KSP 33

__global__ __launch_bounds__(256) void attn_bucket_kernel()
{
    __shared__ float qsh[32 * QS];
    __shared__ float ksh[64 * KSK];
    __shared__ float vsh[32 * QS];
    __shared__ float psh[32 * KSP];
    __shared__ int   qid[32];

    const int bucket = blockIdx.x;
    const int combo  = blockIdx.y;
    const int hash = combo >> 4;
    const int b    = (combo >> 3) & 1;
    const int h    = combo & 7;
    const int tid  = threadIdx.x;
    const int tx = tid & 15, ty = tid >> 4;

    const int qs = g_qstart[combo][bucket];
    const int nq = g_qstart[combo][bucket + 1] - qs;
    if (nq == 0) return;
    const int ks = g_kstart[combo][bucket];
    const int kn = g_kstart[combo][bucket + 1] - ks;

    const unsigned short* qlist = g_qlist + combo * T_LEN;
    const unsigned short* klist = g_klist + combo * T_LEN;

    float* Op = g_att[hash] + (size_t)b * T_LEN * EMB + h * HDIM;

    if (bucket >= 32 || kn == 0) {
        for (int idx = tid; idx < nq * 16; idx += 256) {
            int qi = idx >> 4, sl = idx & 15;
            int t = qlist[qs + qi];
            *reinterpret_cast<float4*>(Op + (size_t)t * EMB + sl * 4) =
                make_float4(0.f, 0.f, 0.f, 0.f);
        }
        return;
    }

    const float* Qp = g_Q + (size_t)b * T_LEN * EMB + h * HDIM;
    const float* Kp = g_K + (size_t)b * T_LEN * EMB + h * HDIM;
    const float* Vp = g_V + (size_t)b * T_LEN * EMB + h * HDIM;

    for (int q0 = 0; q0 < nq; q0 += 32) {
        const int cq = min(32, nq - q0);
        __syncthreads();
        for (int task = tid; task < 512; task += 256) {
            int row = task >> 4, slot = task & 15;
            if (row < cq) {
                int t = qlist[qs + q0 + row];
                if (slot == 0) qid[row] = t;
                float4 v4 = *reinterpret_cast<const float4*>(Qp + (size_t)t * EMB + slot * 4);
                float* d = &qsh[row * QS + slot * 4];
                d[0] = v4.x; d[1] = v4.y; d[2] = v4.z; d[3] = v4.w;
            }
        }
        __syncthreads();

        float m[2], l[2], o[2][4];
#pragma unroll
        for (int i = 0; i < 2; i++) {
            m[i] = -INFINITY; l[i] = 0.f;
#pragma unroll
            for (int d = 0; d < 4; d++) o[i][d] = 0.f;
        }

        for (int k0 = 0; k0 < kn; k0 += 32) {
            const int cnk = min(32, kn - k0);
            __syncthreads();
            for (int task = tid; task < 512; task += 256) {
                int row = task >> 4, slot = task & 15;
                float* dv = &vsh[row * QS + slot * 4];
                if (row < cnk) {
                    int t = klist[ks + k0 + row];
                    float4 k4 = *reinterpret_cast<const float4*>(Kp + (size_t)t * EMB + slot * 4);
                    ksh[(slot * 4 + 0) * KSK + row] = k4.x;
                    ksh[(slot * 4 + 1) * KSK + row] = k4.y;
                    ksh[(slot * 4 + 2) * KSK + row] = k4.z;
                    ksh[(slot * 4 + 3) * KSK + row] = k4.w;
                    float4 v4 = *reinterpret_cast<const float4*>(Vp + (size_t)t * EMB + slot * 4);
                    dv[0] = v4.x; dv[1] = v4.y; dv[2] = v4.z; dv[3] = v4.w;
                } else {
                    dv[0] = 0.f; dv[1] = 0.f; dv[2] = 0.f; dv[3] = 0.f;
                }
            }
            __syncthreads();

            float s00 = 0.f, s01 = 0.f, s10 = 0.f, s11 = 0.f;
            const float* q0p = &qsh[(ty * 2 + 0) * QS];
            const float* q1p = &qsh[(ty * 2 + 1) * QS];
#pragma unroll 8
            for (int k = 0; k < 64; k += 2) {
                float2 a0 = *reinterpret_cast<const float2*>(&q0p[k]);
                float2 a1 = *reinterpret_cast<const float2*>(&q1p[k]);
                float2 b0 = *reinterpret_cast<const float2*>(&ksh[k * KSK + tx * 2]);
                float2 b1 = *reinterpret_cast<const float2*>(&ksh[(k + 1) * KSK + tx * 2]);
                s00 += a0.x * b0.x + a0.y * b1.x;
                s01 += a0.x * b0.y + a0.y * b1.y;
                s10 += a1.x * b0.x + a1.y * b1.x;
                s11 += a1.x * b0.y + a1.y * b1.y;
            }
            const bool c0 = (tx * 2 + 0) < cnk;
            const bool c1 = (tx * 2 + 1) < cnk;
            float s4[2][2];
            s4[0][0] = c0 ? s00 * 0.125f : -INFINITY;
            s4[0][1] = c1 ? s01 * 0.125f : -INFINITY;
            s4[1][0] = c0 ? s10 * 0.125f : -INFINITY;
            s4[1][1] = c1 ? s11 * 0.125f : -INFINITY;

#pragma unroll
            for (int i = 0; i < 2; i++) {
                float cm = fmaxf(s4[i][0], s4[i][1]);
#pragma unroll
                for (int off = 1; off < 16; off <<= 1)
                    cm = fmaxf(cm, __shfl_xor_sync(FULLMASK, cm, off));
                float mn = fmaxf(m[i], cm);
                float corr = __expf(m[i] - mn);
                m[i] = mn;
                float w0 = __expf(s4[i][0] - mn);
                float w1 = __expf(s4[i][1] - mn);
                s4[i][0] = w0; s4[i][1] = w1;
                float ps = w0 + w1;
#pragma unroll
                for (int off = 1; off < 16; off <<= 1)
                    ps += __shfl_xor_sync(FULLMASK, ps, off);
                l[i] = l[i] * corr + ps;
#pragma unroll
                for (int d = 0; d < 4; d++) o[i][d] *= corr;
            }
#pragma unroll
            for (int i = 0; i < 2; i++) {
                psh[(ty * 2 + i) * KSP + tx * 2 + 0] = s4[i][0];
                psh[(ty * 2 + i) * KSP + tx * 2 + 1] = s4[i][1];
            }
            __syncthreads();
            const float* p0 = &psh[(ty * 2 + 0) * KSP];
            const float* p1 = &psh[(ty * 2 + 1) * KSP];
#pragma unroll 8
            for (int j = 0; j < 32; j++) {
                float pv0 = p0[j];
                float pv1 = p1[j];
                float4 vv = *reinterpret_cast<const float4*>(&vsh[j * QS + tx * 4]);
                o[0][0] += pv0 * vv.x; o[0][1] += pv0 * vv.y;
                o[0][2] += pv0 * vv.z; o[0][3] += pv0 * vv.w;
                o[1][0] += pv1 * vv.x; o[1][1] += pv1 * vv.y;
                o[1][2] += pv1 * vv.z; o[1][3] += pv1 * vv.w;
            }
        }

#pragma unroll
        for (int i = 0; i < 2; i++) {
            int row = ty * 2 + i;
            if (row < cq) {
                float inv = 1.f / l[i];
                int t = qid[row];
                float4 v;
                v.x = o[i][0] * inv; v.y = o[i][1] * inv;
                v.z = o[i][2] * inv; v.w = o[i][3] * inv;
                *reinterpret_cast<float4*>(Op + (size_t)t * EMB + tx * 4) = v;
            }
        }
    }
}

// ---------------------------------------------------------------------------
extern "C" void kernel_launch(void* const* d_in, const int* in_sizes, int n_in,
                              void* d_out, int out_size)
{
    (void)in_sizes; (void)n_in; (void)out_size;
    const float* query = (const float*)d_in[0];
    const float* key   = (const float*)d_in[1];
    const float* value = (const float*)d_in[2];
    const float* Wq = (const float*)d_in[3];
    const float* bq = (const float*)d_in[4];
    const float* Wk = (const float*)d_in[5];
    const float* bk = (const float*)d_in[6];
    const float* Wv = (const float*)d_in[7];
    const float* bv = (const float*)d_in[8];
    const float* Wo = (const float*)d_in[9];
    const float* bo = (const float*)d_in[10];
    const float* lshW = (const float*)d_in[11];
    const float* lshb = (const float*)d_in[12];
    float* out = (float*)d_out;

    cudaFuncSetAttribute(gemm_qk, cudaFuncAttributeMaxDynamicSharedMemorySize, QKV_SMEM);
    cudaFuncSetAttribute(gemm_tc<0>, cudaFuncAttributeMaxDynamicSharedMemorySize, TC_SMEM3);
    cudaFuncSetAttribute(gemm_tc<1>, cudaFuncAttributeMaxDynamicSharedMemorySize, TC_SMEM3);

    split_v_kernel<<<ROWS * (EMB / 4) / 256, 256>>>(value);
    split_w_kernel<<<EMB * (EMB / 4) / 256, 256>>>(Wv);

    gemm_qk<<<dim3(EMB / 128, ROWS / 128, 2), 256, QKV_SMEM>>>(query, key,
                                                               Wq, Wk, bq, bk);
    gemm_tc<0><<<dim3(EMB / 128, ROWS / 128), 256, TC_SMEM3>>>(nullptr, bv);
    hash_gemm<<<dim3(512, 2), 256>>>(lshW, lshb);
    bucketize_kernel<<<32, 256>>>();
    attn_bucket_kernel<<<dim3(64, 32), 256>>>();

    split_att_kernel<<<ROWS * (EMB / 4) / 256, 256>>>();
    split_w_kernel<<<EMB * (EMB / 4) / 256, 256>>>(Wo);
    gemm_tc<1><<<dim3(EMB / 128, ROWS / 128), 256, TC_SMEM3>>>(out, bo);
}

// round 13
// speedup vs baseline: 1.5573x; 1.5573x over previous
#include <cuda_runtime.h>
#include <cuda_bf16.h>
#include <mma.h>
#include <cstdint>

using namespace nvcuda;

#define T_LEN 2048
#define B_SZ  2
#define EMB   512
#define ROWS  4096       // B*T
#define HEADS 8
#define HDIM  64
#define NHASH 2
#define FULLMASK 0xffffffffu

// ---------------------------------------------------------------------------
// Scratch
// ---------------------------------------------------------------------------
__device__ float g_Q[ROWS * EMB];
__device__ float g_K[ROWS * EMB];
__device__ float g_V[ROWS * EMB];
__device__ unsigned char g_qh[NHASH * B_SZ * HEADS * T_LEN];
__device__ unsigned char g_kh[NHASH * B_SZ * HEADS * T_LEN];
__device__ float g_att[NHASH][ROWS * EMB];
__device__ int g_qstart[32][65];
__device__ int g_kstart[32][65];
__device__ unsigned short g_qlist[32 * T_LEN];
__device__ unsigned short g_klist[32 * T_LEN];
// pre-split bf16 operands
__device__ __nv_bfloat16 g_Ah[ROWS * EMB];
__device__ __nv_bfloat16 g_Al[ROWS * EMB];
__device__ __nv_bfloat16 g_Wh[EMB * EMB];    // Wv
__device__ __nv_bfloat16 g_Wl[EMB * EMB];
__device__ __nv_bfloat16 g_W2h[EMB * EMB];   // Wo
__device__ __nv_bfloat16 g_W2l[EMB * EMB];

// ---------------------------------------------------------------------------
// f32x2 helper (exact-fp32 Q/K + hash path)
// ---------------------------------------------------------------------------
__device__ __forceinline__ float2 ffma2(float2 a, float2 b, float2 c)
{
    unsigned long long ua = *reinterpret_cast<unsigned long long*>(&a);
    unsigned long long ub = *reinterpret_cast<unsigned long long*>(&b);
    unsigned long long uc = *reinterpret_cast<unsigned long long*>(&c);
    unsigned long long ud;
    asm("fma.rn.f32x2 %0, %1, %2, %3;" : "=l"(ud) : "l"(ua), "l"(ub), "l"(uc));
    return *reinterpret_cast<float2*>(&ud);
}

#define AS2_STRIDE 258
#define BSX_STRIDE 132
#define QKV_SMEM ((2 * 16 * AS2_STRIDE + 2 * 16 * BSX_STRIDE) * 4)

__device__ __forceinline__ void tile_fma2(const float* __restrict__ A2,
                                          const float* __restrict__ Bx,
                                          float2 acc[8][4], int tx, int ty)
{
#pragma unroll
    for (int k = 0; k < 16; k++) {
        const float* ar = A2 + k * AS2_STRIDE;
        const float* br = Bx + k * BSX_STRIDE;
        float2 avd[8], bv2[4];
#pragma unroll
        for (int i = 0; i < 8; i++)
            avd[i] = *reinterpret_cast<const float2*>(ar + 2 * (ty * 8 + i));
#pragma unroll
        for (int p = 0; p < 4; p++)
            bv2[p] = *reinterpret_cast<const float2*>(br + p * 32 + tx * 2);
#pragma unroll
        for (int i = 0; i < 8; i++)
#pragma unroll
            for (int p = 0; p < 4; p++)
                acc[i][p] = ffma2(avd[i], bv2[p], acc[i][p]);
    }
}

// ---------------------------------------------------------------------------
// Kernel 1: Q/K projections (EXACT fp32 — LSH argmax is flip-sensitive).
// ---------------------------------------------------------------------------
__global__ __launch_bounds__(256, 2) void gemm_qk(
    const float* __restrict__ Xq, const float* __restrict__ Xk,
    const float* __restrict__ Wq, const float* __restrict__ Wk,
    const float* __restrict__ bq, const float* __restrict__ bk)
{
    extern __shared__ float sm[];
    float* A2 = sm;
    float* Bx = sm + 2 * 16 * AS2_STRIDE;

    const int tid = threadIdx.x;
    const int bn = blockIdx.x;
    const int bm = blockIdx.y;
    const int z  = blockIdx.z;
    const int tx = tid & 15, ty = tid >> 4;

    const float* X = (z == 0) ? Xq : Xk;
    const float* W = (z == 0) ? Wq : Wk;
    const float* bias = (z == 0) ? bq : bk;
    float* outp = (z == 0) ? g_Q : g_K;

    const int rr = tid >> 1;
    const int kb = (tid & 1) * 8;
    const int r = bm * 128 + rr;
    const int src = (r & 1) * T_LEN + (r >> 1);
    const float* Aptr = X + (size_t)src * EMB + kb;
    const float* Bptr = W + (size_t)(bn * 128 + rr) * EMB + kb;

    float2 acc[8][4];
#pragma unroll
    for (int i = 0; i < 8; i++)
#pragma unroll
        for (int p = 0; p < 4; p++) acc[i][p] = make_float2(0.f, 0.f);

    float4 ra0 = *reinterpret_cast<const float4*>(Aptr);
    float4 ra1 = *reinterpret_cast<const float4*>(Aptr + 4);
    float4 rb0 = *reinterpret_cast<const float4*>(Bptr);
    float4 rb1 = *reinterpret_cast<const float4*>(Bptr + 4);

    {
        float va[8] = {ra0.x, ra0.y, ra0.z, ra0.w, ra1.x, ra1.y, ra1.z, ra1.w};
        float vb[8] = {rb0.x, rb0.y, rb0.z, rb0.w, rb1.x, rb1.y, rb1.z, rb1.w};
#pragma unroll
        for (int c = 0; c < 8; c++) {
            float* pa = A2 + (kb + c) * AS2_STRIDE + 2 * rr;
            pa[0] = va[c]; pa[1] = va[c];
            Bx[(kb + c) * BSX_STRIDE + rr] = vb[c];
        }
    }
    __syncthreads();

    const int NS = EMB / 16;
    for (int s = 0; s < NS; s++) {
        const int cur = s & 1;
        if (s + 1 < NS) {
            ra0 = *reinterpret_cast<const float4*>(Aptr + (s + 1) * 16);
            ra1 = *reinterpret_cast<const float4*>(Aptr + (s + 1) * 16 + 4);
            rb0 = *reinterpret_cast<const float4*>(Bptr + (s + 1) * 16);
            rb1 = *reinterpret_cast<const float4*>(Bptr + (s + 1) * 16 + 4);
        }
        tile_fma2(A2 + cur * 16 * AS2_STRIDE, Bx + cur * 16 * BSX_STRIDE, acc, tx, ty);
        if (s + 1 < NS) {
            __syncthreads();
            const int nxt = cur ^ 1;
            float va[8] = {ra0.x, ra0.y, ra0.z, ra0.w, ra1.x, ra1.y, ra1.z, ra1.w};
            float vb[8] = {rb0.x, rb0.y, rb0.z, rb0.w, rb1.x, rb1.y, rb1.z, rb1.w};
#pragma unroll
            for (int c = 0; c < 8; c++) {
                float* pa = A2 + (nxt * 16 + kb + c) * AS2_STRIDE + 2 * rr;
                pa[0] = va[c]; pa[1] = va[c];
                Bx[(nxt * 16 + kb + c) * BSX_STRIDE + rr] = vb[c];
            }
            __syncthreads();
        }
    }

    float2 bb2[4];
#pragma unroll
    for (int p = 0; p < 4; p++)
        bb2[p] = *reinterpret_cast<const float2*>(bias + bn * 128 + p * 32 + tx * 2);
#pragma unroll
    for (int i = 0; i < 8; i++) {
        int ro = bm * 128 + ty * 8 + i;
        float* op = outp + (size_t)ro * EMB + bn * 128;
#pragma unroll
        for (int p = 0; p < 4; p++) {
            float2 v = acc[i][p];
            v.x += bb2[p].x; v.y += bb2[p].y;
            *reinterpret_cast<float2*>(op + p * 32 + tx * 2) = v;
        }
    }
}

// ---------------------------------------------------------------------------
// Split kernels: fp32 -> (hi, lo) bf16 pairs.
// ---------------------------------------------------------------------------
__device__ __forceinline__ void split_store4(__nv_bfloat16* dh, __nv_bfloat16* dl,
                                             float4 v)
{
    float h0 = __bfloat162float(__float2bfloat16(v.x));
    float h1 = __bfloat162float(__float2bfloat16(v.y));
    float h2 = __bfloat162float(__float2bfloat16(v.z));
    float h3 = __bfloat162float(__float2bfloat16(v.w));
    __nv_bfloat162 a, b;
    a.x = __float2bfloat16(v.x); a.y = __float2bfloat16(v.y);
    b.x = __float2bfloat16(v.z); b.y = __float2bfloat16(v.w);
    *reinterpret_cast<__nv_bfloat162*>(dh)     = a;
    *reinterpret_cast<__nv_bfloat162*>(dh + 2) = b;
    __nv_bfloat162 c, d;
    c.x = __float2bfloat16(v.x - h0); c.y = __float2bfloat16(v.y - h1);
    d.x = __float2bfloat16(v.z - h2); d.y = __float2bfloat16(v.w - h3);
    *reinterpret_cast<__nv_bfloat162*>(dl)     = c;
    *reinterpret_cast<__nv_bfloat162*>(dl + 2) = d;
}

__global__ __launch_bounds__(256) void split_v_kernel(const float* __restrict__ value)
{
    int idx = blockIdx.x * 256 + threadIdx.x;
    int f = idx >> 7;
    int c = (idx & 127) * 4;
    int srcr = (f & 1) * T_LEN + (f >> 1);
    float4 v = *reinterpret_cast<const float4*>(value + (size_t)srcr * EMB + c);
    split_store4(g_Ah + (size_t)f * EMB + c, g_Al + (size_t)f * EMB + c, v);
}

// which = 0 -> g_Wh/g_Wl (Wv), which = 1 -> g_W2h/g_W2l (Wo)
__global__ __launch_bounds__(256) void split_w_kernel(const float* __restrict__ W,
                                                      int which)
{
    int idx = blockIdx.x * 256 + threadIdx.x;
    int rr = idx >> 7;
    int c = (idx & 127) * 4;
    float4 v = *reinterpret_cast<const float4*>(W + (size_t)rr * EMB + c);
    __nv_bfloat16* dh = (which == 0) ? g_Wh : g_W2h;
    __nv_bfloat16* dl = (which == 0) ? g_Wl : g_W2l;
    split_store4(dh + (size_t)rr * EMB + c, dl + (size_t)rr * EMB + c, v);
}

__global__ __launch_bounds__(256) void split_att_kernel()
{
    int idx = blockIdx.x * 256 + threadIdx.x;
    int f = idx >> 7;
    int c = (idx & 127) * 4;
    size_t o = (size_t)f * EMB + c;
    float4 x = *reinterpret_cast<const float4*>(&g_att[0][o]);
    float4 y = *reinterpret_cast<const float4*>(&g_att[1][o]);
    x.x = 0.5f * (x.x + y.x); x.y = 0.5f * (x.y + y.y);
    x.z = 0.5f * (x.z + y.z); x.w = 0.5f * (x.w + y.w);
    split_store4(g_Ah + o, g_Al + o, x);
}

// ---------------------------------------------------------------------------
// Kernel TC: bf16 split tensor-core GEMM (EXACT revert of the 301.5 version;
// only delta: MODE selects the pre-split weight buffer pair).
// ---------------------------------------------------------------------------
#define TCS2 72
#define OBS  72
#define TC_SMEM2 (4 * 128 * TCS2 * 2)    // 73728 B

template<int MODE>
__global__ __launch_bounds__(256) void gemm_tc(float* __restrict__ out,
                                               const float* __restrict__ bias)
{
    extern __shared__ char raw[];
    __nv_bfloat16* Ah = reinterpret_cast<__nv_bfloat16*>(raw);
    __nv_bfloat16* Al = Ah + 128 * TCS2;
    __nv_bfloat16* Bh = Al + 128 * TCS2;
    __nv_bfloat16* Bl = Bh + 128 * TCS2;
    float* obuf = reinterpret_cast<float*>(raw);

    const int tid = threadIdx.x;
    const int bn = blockIdx.x;
    const int bm = blockIdx.y;
    const int w  = tid >> 5;
    const int wm = w & 3;
    const int wn = w >> 2;

    const __nv_bfloat16* GWh = (MODE == 0) ? g_Wh : g_W2h;
    const __nv_bfloat16* GWl = (MODE == 0) ? g_Wl : g_W2l;

    wmma::fragment<wmma::accumulator, 16, 16, 16, float> acc[2][4];
#pragma unroll
    for (int im = 0; im < 2; im++)
#pragma unroll
        for (int jn = 0; jn < 4; jn++) wmma::fill_fragment(acc[im][jn], 0.f);

    for (int ks = 0; ks < EMB; ks += 64) {
        __syncthreads();
#pragma unroll
        for (int i = 0; i < 4; i++) {
            int idx = tid + i * 256;
            int row = idx >> 3;
            int seg = idx & 7;
            size_t ga = (size_t)(bm * 128 + row) * EMB + ks + seg * 8;
            size_t gb = (size_t)(bn * 128 + row) * EMB + ks + seg * 8;
            int so = row * TCS2 + seg * 8;
            *reinterpret_cast<uint4*>(Ah + so) = *reinterpret_cast<const uint4*>(g_Ah + ga);
            *reinterpret_cast<uint4*>(Al + so) = *reinterpret_cast<const uint4*>(g_Al + ga);
            *reinterpret_cast<uint4*>(Bh + so) = *reinterpret_cast<const uint4*>(GWh + gb);
            *reinterpret_cast<uint4*>(Bl + so) = *reinterpret_cast<const uint4*>(GWl + gb);
        }
        __syncthreads();

#pragma unroll
        for (int kk = 0; kk < 4; kk++) {
            wmma::fragment<wmma::matrix_a, 16, 16, 16, __nv_bfloat16, wmma::row_major> ah[2], al[2];
#pragma unroll
            for (int im = 0; im < 2; im++) {
                wmma::load_matrix_sync(ah[im], Ah + (wm * 32 + im * 16) * TCS2 + kk * 16, TCS2);
                wmma::load_matrix_sync(al[im], Al + (wm * 32 + im * 16) * TCS2 + kk * 16, TCS2);
            }
#pragma unroll
            for (int jn = 0; jn < 4; jn++) {
                wmma::fragment<wmma::matrix_b, 16, 16, 16, __nv_bfloat16, wmma::col_major> bh, bl;
                wmma::load_matrix_sync(bh, Bh + (wn * 64 + jn * 16) * TCS2 + kk * 16, TCS2);
                wmma::load_matrix_sync(bl, Bl + (wn * 64 + jn * 16) * TCS2 + kk * 16, TCS2);
#pragma unroll
                for (int im = 0; im < 2; im++) {
                    wmma::mma_sync(acc[im][jn], ah[im], bh, acc[im][jn]);
                    wmma::mma_sync(acc[im][jn], ah[im], bl, acc[im][jn]);
                    wmma::mma_sync(acc[im][jn], al[im], bh, acc[im][jn]);
                }
            }
        }
    }

    float* dstp = (MODE == 0) ? g_V : out;

#pragma unroll
    for (int half = 0; half < 2; half++) {
        __syncthreads();
        if (wn == half) {
#pragma unroll
            for (int im = 0; im < 2; im++)
#pragma unroll
                for (int jn = 0; jn < 4; jn++)
                    wmma::store_matrix_sync(obuf + (wm * 32 + im * 16) * OBS + jn * 16,
                                            acc[im][jn], OBS, wmma::mem_row_major);
        }
        __syncthreads();
#pragma unroll
        for (int it = 0; it < 8; it++) {
            int idx = tid + it * 256;
            int row = idx >> 4;
            int c4  = idx & 15;
            float4 v = *reinterpret_cast<const float4*>(&obuf[row * OBS + c4 * 4]);
            int colg = bn * 128 + half * 64 + c4 * 4;
            v.x += bias[colg + 0]; v.y += bias[colg + 1];
            v.z += bias[colg + 2]; v.w += bias[colg + 3];
            int ro = bm * 128 + row;
            int g = (MODE == 1) ? ((ro & 2047) * B_SZ + (ro >> 11)) : ro;
            *reinterpret_cast<float4*>(dstp + (size_t)g * EMB + colg) = v;
        }
    }
}

// ---------------------------------------------------------------------------
// Kernel 2: LSH hashing GEMM (64x128 tile) + fused argmax (exact fp32),
// register double-buffered (same pattern as gemm_qk).
// ---------------------------------------------------------------------------
__global__ __launch_bounds__(256) void hash_gemm(const float* __restrict__ lshW,
                                                 const float* __restrict__ lshb)
{
    __shared__ float As2h[2][16][130];
    __shared__ float Bsh[2][16][132];
    const int tid = threadIdx.x;
    const int bm = blockIdx.x;
    const int tensor = blockIdx.y;
    const int tx = tid & 15, ty = tid >> 4;

    const float* A = tensor ? g_K : g_Q;
    unsigned char* dst = tensor ? g_kh : g_qh;

    const int arr = tid >> 2, ak4 = tid & 3;     // A staging coords
    const int br0 = (tid * 2) >> 2, bk40 = (tid * 2) & 3;       // B slot 0
    const int br1 = (tid * 2 + 1) >> 2, bk41 = (tid * 2 + 1) & 3; // B slot 1
    const float* Abase = A + (size_t)(bm * 64 + arr) * 64 + ak4 * 4;
    const float* B0 = lshW + (size_t)br0 * 64 + bk40 * 4;
    const float* B1 = lshW + (size_t)br1 * 64 + bk41 * 4;

    float2 acc[4][4];
#pragma unroll
    for (int i = 0; i < 4; i++)
#pragma unroll
        for (int p = 0; p < 4; p++) acc[i][p] = make_float2(0.f, 0.f);

    float4 ra = *reinterpret_cast<const float4*>(Abase);
    float4 rb0 = *reinterpret_cast<const float4*>(B0);
    float4 rb1 = *reinterpret_cast<const float4*>(B1);
    {
        float va[4] = {ra.x, ra.y, ra.z, ra.w};
#pragma unroll
        for (int c = 0; c < 4; c++) {
            As2h[0][ak4 * 4 + c][2 * arr] = va[c];
            As2h[0][ak4 * 4 + c][2 * arr + 1] = va[c];
        }
        Bsh[0][bk40 * 4 + 0][br0] = rb0.x; Bsh[0][bk40 * 4 + 1][br0] = rb0.y;
        Bsh[0][bk40 * 4 + 2][br0] = rb0.z; Bsh[0][bk40 * 4 + 3][br0] = rb0.w;
        Bsh[0][bk41 * 4 + 0][br1] = rb1.x; Bsh[0][bk41 * 4 + 1][br1] = rb1.y;
        Bsh[0][bk41 * 4 + 2][br1] = rb1.z; Bsh[0][bk41 * 4 + 3][br1] = rb1.w;
    }
    __syncthreads();

    for (int s = 0; s < 4; s++) {
        const int cur = s & 1;
        if (s + 1 < 4) {
            ra  = *reinterpret_cast<const float4*>(Abase + (s + 1) * 16);
            rb0 = *reinterpret_cast<const float4*>(B0 + (s + 1) * 16);
            rb1 = *reinterpret_cast<const float4*>(B1 + (s + 1) * 16);
        }
#pragma unroll
        for (int k = 0; k < 16; k++) {
            float2 avd[4], bv2[4];
#pragma unroll
            for (int i = 0; i < 4; i++)
                avd[i] = *reinterpret_cast<const float2*>(&As2h[cur][k][2 * (ty * 4 + i)]);
#pragma unroll
            for (int p = 0; p < 4; p++)
                bv2[p] = *reinterpret_cast<const float2*>(&Bsh[cur][k][p * 32 + tx * 2]);
#pragma unroll
            for (int i = 0; i < 4; i++)
#pragma unroll
                for (int p = 0; p < 4; p++)
                    acc[i][p] = ffma2(avd[i], bv2[p], acc[i][p]);
        }
        if (s + 1 < 4) {
            __syncthreads();
            const int nxt = cur ^ 1;
            float va[4] = {ra.x, ra.y, ra.z, ra.w};
#pragma unroll
            for (int c = 0; c < 4; c++) {
                As2h[nxt][ak4 * 4 + c][2 * arr] = va[c];
                As2h[nxt][ak4 * 4 + c][2 * arr + 1] = va[c];
            }
            Bsh[nxt][bk40 * 4 + 0][br0] = rb0.x; Bsh[nxt][bk40 * 4 + 1][br0] = rb0.y;
            Bsh[nxt][bk40 * 4 + 2][br0] = rb0.z; Bsh[nxt][bk40 * 4 + 3][br0] = rb0.w;
            Bsh[nxt][bk41 * 4 + 0][br1] = rb1.x; Bsh[nxt][bk41 * 4 + 1][br1] = rb1.y;
            Bsh[nxt][bk41 * 4 + 2][br1] = rb1.z; Bsh[nxt][bk41 * 4 + 3][br1] = rb1.w;
            __syncthreads();
        }
    }

    float2 bb2[4];
#pragma unroll
    for (int p = 0; p < 4; p++)
        bb2[p] = *reinterpret_cast<const float2*>(lshb + p * 32 + tx * 2);

#pragma unroll
    for (int i = 0; i < 4; i++) {
        const int m  = bm * 64 + ty * 4 + i;
        const int r  = m >> 3, h = m & 7;
        const int nb = r >> 11, nt = r & 2047;
#pragma unroll
        for (int hh = 0; hh < 2; hh++) {
            float2 c0 = acc[i][2 * hh];
            float2 c1 = acc[i][2 * hh + 1];
            c0.x += bb2[2 * hh].x;     c0.y += bb2[2 * hh].y;
            c1.x += bb2[2 * hh + 1].x; c1.y += bb2[2 * hh + 1].y;
            float bvv = c0.x; int bi = tx * 2;
            if (c0.y > bvv) { bvv = c0.y; bi = tx * 2 + 1; }
            if (c1.x > bvv) { bvv = c1.x; bi = 32 + tx * 2; }
            if (c1.y > bvv) { bvv = c1.y; bi = 33 + tx * 2; }
#pragma unroll
            for (int off = 1; off < 16; off <<= 1) {
                float ov = __shfl_xor_sync(FULLMASK, bvv, off);
                int   oi = __shfl_xor_sync(FULLMASK, bi, off);
                if (ov > bvv || (ov == bvv && oi < bi)) { bvv = ov; bi = oi; }
            }
            if (tx == 0)
                dst[((hh * B_SZ + nb) * HEADS + h) * T_LEN + nt] = (unsigned char)bi;
        }
    }
}

// ---------------------------------------------------------------------------
// Kernel 3: bucketize — grid (32 combos, 2 tensors)
// ---------------------------------------------------------------------------
__global__ __launch_bounds__(256) void bucketize_kernel()
{
    __shared__ int cnt[64];
    __shared__ int off[64];
    const int combo = blockIdx.x;
    const int tensor = blockIdx.y;
    const int tid = threadIdx.x;

    const unsigned char* hsrc = (tensor ? g_kh : g_qh) + combo * T_LEN;
    int* startp = tensor ? g_kstart[combo] : g_qstart[combo];
    unsigned short* listp = (tensor ? g_klist : g_qlist) + combo * T_LEN;

    if (tid < 64) cnt[tid] = 0;
    __syncthreads();

    for (int i = tid; i < T_LEN; i += 256)
        atomicAdd(&cnt[hsrc[i]], 1);
    __syncthreads();

    if (tid == 0) {
        int s = 0;
        for (int j = 0; j < 64; j++) { startp[j] = s; off[j] = s; s += cnt[j]; }
        startp[64] = s;
    }
    __syncthreads();

    for (int i = tid; i < T_LEN; i += 256) {
        int p = atomicAdd(&off[hsrc[i]], 1);
        listp[p] = (unsigned short)i;
    }
}

// ---------------------------------------------------------------------------
// Kernel 4: per-bucket flash attention, 32x32 tiles.
// ---------------------------------------------------------------------------
#define QS  68
#define KSK 34
#define KSP 33

__global__ __launch_bounds__(256) void attn_bucket_kernel()
{
    __shared__ float qsh[32 * QS];
    __shared__ float ksh[64 * KSK];
    __shared__ float vsh[32 * QS];
    __shared__ float psh[32 * KSP];
    __shared__ int   qid[32];

    const int bucket = blockIdx.x;
    const int combo  = blockIdx.y;
    const int hash = combo >> 4;
    const int b    = (combo >> 3) & 1;
    const int h    = combo & 7;
    const int tid  = threadIdx.x;
    const int tx = tid & 15, ty = tid >> 4;

    const int qs = g_qstart[combo][bucket];
    const int nq = g_qstart[combo][bucket + 1] - qs;
    if (nq == 0) return;
    const int ks = g_kstart[combo][bucket];
    const int kn = g_kstart[combo][bucket + 1] - ks;

    const unsigned short* qlist = g_qlist + combo * T_LEN;
    const unsigned short* klist = g_klist + combo * T_LEN;

    float* Op = g_att[hash] + (size_t)b * T_LEN * EMB + h * HDIM;

    if (bucket >= 32 || kn == 0) {
        for (int idx = tid; idx < nq * 16; idx += 256) {
            int qi = idx >> 4, sl = idx & 15;
            int t = qlist[qs + qi];
            *reinterpret_cast<float4*>(Op + (size_t)t * EMB + sl * 4) =
                make_float4(0.f, 0.f, 0.f, 0.f);
        }
        return;
    }

    const float* Qp = g_Q + (size_t)b * T_LEN * EMB + h * HDIM;
    const float* Kp = g_K + (size_t)b * T_LEN * EMB + h * HDIM;
    const float* Vp = g_V + (size_t)b * T_LEN * EMB + h * HDIM;

    for (int q0 = 0; q0 < nq; q0 += 32) {
        const int cq = min(32, nq - q0);
        __syncthreads();
        for (int task = tid; task < 512; task += 256) {
            int row = task >> 4, slot = task & 15;
            if (row < cq) {
                int t = qlist[qs + q0 + row];
                if (slot == 0) qid[row] = t;
                float4 v4 = *reinterpret_cast<const float4*>(Qp + (size_t)t * EMB + slot * 4);
                float* d = &qsh[row * QS + slot * 4];
                d[0] = v4.x; d[1] = v4.y; d[2] = v4.z; d[3] = v4.w;
            }
        }
        __syncthreads();

        float m[2], l[2], o[2][4];
#pragma unroll
        for (int i = 0; i < 2; i++) {
            m[i] = -INFINITY; l[i] = 0.f;
#pragma unroll
            for (int d = 0; d < 4; d++) o[i][d] = 0.f;
        }

        for (int k0 = 0; k0 < kn; k0 += 32) {
            const int cnk = min(32, kn - k0);
            __syncthreads();
            for (int task = tid; task < 512; task += 256) {
                int row = task >> 4, slot = task & 15;
                float* dv = &vsh[row * QS + slot * 4];
                if (row < cnk) {
                    int t = klist[ks + k0 + row];
                    float4 k4 = *reinterpret_cast<const float4*>(Kp + (size_t)t * EMB + slot * 4);
                    ksh[(slot * 4 + 0) * KSK + row] = k4.x;
                    ksh[(slot * 4 + 1) * KSK + row] = k4.y;
                    ksh[(slot * 4 + 2) * KSK + row] = k4.z;
                    ksh[(slot * 4 + 3) * KSK + row] = k4.w;
                    float4 v4 = *reinterpret_cast<const float4*>(Vp + (size_t)t * EMB + slot * 4);
                    dv[0] = v4.x; dv[1] = v4.y; dv[2] = v4.z; dv[3] = v4.w;
                } else {
                    dv[0] = 0.f; dv[1] = 0.f; dv[2] = 0.f; dv[3] = 0.f;
                }
            }
            __syncthreads();

            float s00 = 0.f, s01 = 0.f, s10 = 0.f, s11 = 0.f;
            const float* q0p = &qsh[(ty * 2 + 0) * QS];
            const float* q1p = &qsh[(ty * 2 + 1) * QS];
#pragma unroll 8
            for (int k = 0; k < 64; k += 2) {
                float2 a0 = *reinterpret_cast<const float2*>(&q0p[k]);
                float2 a1 = *reinterpret_cast<const float2*>(&q1p[k]);
                float2 b0 = *reinterpret_cast<const float2*>(&ksh[k * KSK + tx * 2]);
                float2 b1 = *reinterpret_cast<const float2*>(&ksh[(k + 1) * KSK + tx * 2]);
                s00 += a0.x * b0.x + a0.y * b1.x;
                s01 += a0.x * b0.y + a0.y * b1.y;
                s10 += a1.x * b0.x + a1.y * b1.x;
                s11 += a1.x * b0.y + a1.y * b1.y;
            }
            const bool c0 = (tx * 2 + 0) < cnk;
            const bool c1 = (tx * 2 + 1) < cnk;
            float s4[2][2];
            s4[0][0] = c0 ? s00 * 0.125f : -INFINITY;
            s4[0][1] = c1 ? s01 * 0.125f : -INFINITY;
            s4[1][0] = c0 ? s10 * 0.125f : -INFINITY;
            s4[1][1] = c1 ? s11 * 0.125f : -INFINITY;

#pragma unroll
            for (int i = 0; i < 2; i++) {
                float cm = fmaxf(s4[i][0], s4[i][1]);
#pragma unroll
                for (int off = 1; off < 16; off <<= 1)
                    cm = fmaxf(cm, __shfl_xor_sync(FULLMASK, cm, off));
                float mn = fmaxf(m[i], cm);
                float corr = __expf(m[i] - mn);
                m[i] = mn;
                float w0 = __expf(s4[i][0] - mn);
                float w1 = __expf(s4[i][1] - mn);
                s4[i][0] = w0; s4[i][1] = w1;
                float ps = w0 + w1;
#pragma unroll
                for (int off = 1; off < 16; off <<= 1)
                    ps += __shfl_xor_sync(FULLMASK, ps, off);
                l[i] = l[i] * corr + ps;
#pragma unroll
                for (int d = 0; d < 4; d++) o[i][d] *= corr;
            }
#pragma unroll
            for (int i = 0; i < 2; i++) {
                psh[(ty * 2 + i) * KSP + tx * 2 + 0] = s4[i][0];
                psh[(ty * 2 + i) * KSP + tx * 2 + 1] = s4[i][1];
            }
            __syncthreads();
            const float* p0 = &psh[(ty * 2 + 0) * KSP];
            const float* p1 = &psh[(ty * 2 + 1) * KSP];
#pragma unroll 8
            for (int j = 0; j < 32; j++) {
                float pv0 = p0[j];
                float pv1 = p1[j];
                float4 vv = *reinterpret_cast<const float4*>(&vsh[j * QS + tx * 4]);
                o[0][0] += pv0 * vv.x; o[0][1] += pv0 * vv.y;
                o[0][2] += pv0 * vv.z; o[0][3] += pv0 * vv.w;
                o[1][0] += pv1 * vv.x; o[1][1] += pv1 * vv.y;
                o[1][2] += pv1 * vv.z; o[1][3] += pv1 * vv.w;
            }
        }

#pragma unroll
        for (int i = 0; i < 2; i++) {
            int row = ty * 2 + i;
            if (row < cq) {
                float inv = 1.f / l[i];
                int t = qid[row];
                float4 v;
                v.x = o[i][0] * inv; v.y = o[i][1] * inv;
                v.z = o[i][2] * inv; v.w = o[i][3] * inv;
                *reinterpret_cast<float4*>(Op + (size_t)t * EMB + tx * 4) = v;
            }
        }
    }
}

// ---------------------------------------------------------------------------
extern "C" void kernel_launch(void* const* d_in, const int* in_sizes, int n_in,
                              void* d_out, int out_size)
{
    (void)in_sizes; (void)n_in; (void)out_size;
    const float* query = (const float*)d_in[0];
    const float* key   = (const float*)d_in[1];
    const float* value = (const float*)d_in[2];
    const float* Wq = (const float*)d_in[3];
    const float* bq = (const float*)d_in[4];
    const float* Wk = (const float*)d_in[5];
    const float* bk = (const float*)d_in[6];
    const float* Wv = (const float*)d_in[7];
    const float* bv = (const float*)d_in[8];
    const float* Wo = (const float*)d_in[9];
    const float* bo = (const float*)d_in[10];
    const float* lshW = (const float*)d_in[11];
    const float* lshb = (const float*)d_in[12];
    float* out = (float*)d_out;

    cudaFuncSetAttribute(gemm_qk, cudaFuncAttributeMaxDynamicSharedMemorySize, QKV_SMEM);
    cudaFuncSetAttribute(gemm_tc<0>, cudaFuncAttributeMaxDynamicSharedMemorySize, TC_SMEM2);
    cudaFuncSetAttribute(gemm_tc<1>, cudaFuncAttributeMaxDynamicSharedMemorySize, TC_SMEM2);

    // all independent pre-splits up front
    split_v_kernel<<<ROWS * (EMB / 4) / 256, 256>>>(value);
    split_w_kernel<<<EMB * (EMB / 4) / 256, 256>>>(Wv, 0);
    split_w_kernel<<<EMB * (EMB / 4) / 256, 256>>>(Wo, 1);

    gemm_qk<<<dim3(EMB / 128, ROWS / 128, 2), 256, QKV_SMEM>>>(query, key,
                                                               Wq, Wk, bq, bk);
    gemm_tc<0><<<dim3(EMB / 128, ROWS / 128), 256, TC_SMEM2>>>(nullptr, bv);
    hash_gemm<<<dim3(512, 2), 256>>>(lshW, lshb);
    bucketize_kernel<<<dim3(32, 2), 256>>>();
    attn_bucket_kernel<<<dim3(64, 32), 256>>>();

    split_att_kernel<<<ROWS * (EMB / 4) / 256, 256>>>();
    gemm_tc<1><<<dim3(EMB / 128, ROWS / 128), 256, TC_SMEM2>>>(out, bo);
}